// round 1
// baseline (speedup 1.0000x reference)
#include <cuda_runtime.h>
#include <cuda_bf16.h>
#include <math.h>

// ---------------- problem constants ----------------
#define D_     384
#define H_     6
#define HD_    64
#define L_     4
#define B_     8
#define N_     1024
#define SEQ_   1025
#define ROWS_  (B_*SEQ_)     // 8200
#define NC_    2
#define QKV_N  (3*D_)        // 1152
#define FF_    (4*D_)        // 1536

// ---------------- scratch (device globals; no allocation allowed) ----------
__device__ float g_x[ROWS_*D_];
__device__ float g_h[ROWS_*D_];
__device__ float g_qkv[ROWS_*QKV_N];
__device__ float g_attn[ROWS_*D_];
__device__ float g_mlp[ROWS_*FF_];          // also reused as patch-embed tmp
__device__ float g_pw[L_*D_*QKV_N];
__device__ float g_pb[L_*QKV_N];
__device__ float g_lg[B_*N_*NC_];

// ---------------- generic tiled GEMM: C = A(MxK) @ B(KxN) + bias (+res / gelu)
#define EPI_BIAS 0
#define EPI_RES  1
#define EPI_GELU 2

template<int EPI>
__global__ void gemm_k(const float* __restrict__ A, const float* __restrict__ Bm,
                       const float* __restrict__ bias, const float* __restrict__ res,
                       float* __restrict__ C, int M, int N, int K)
{
    __shared__ float As[16][65];
    __shared__ float Bs[16][65];
    int tid = threadIdx.x;                 // 256 threads
    int tx = tid & 15, ty = tid >> 4;
    int row0 = blockIdx.y * 64;
    int col0 = blockIdx.x * 64;
    float acc[4][4] = {};

    for (int k0 = 0; k0 < K; k0 += 16) {
        #pragma unroll
        for (int i = 0; i < 4; i++) {      // A tile: 64 rows x 16 k
            int m = (tid >> 4) + 16*i;
            int k = tid & 15;
            int gr = row0 + m, gk = k0 + k;
            As[k][m] = (gr < M && gk < K) ? A[(size_t)gr*K + gk] : 0.f;
        }
        #pragma unroll
        for (int i = 0; i < 4; i++) {      // B tile: 16 k x 64 n
            int n = tid & 63;
            int k = (tid >> 6) + 4*i;
            int gk = k0 + k, gn = col0 + n;
            Bs[k][n] = (gk < K && gn < N) ? Bm[(size_t)gk*N + gn] : 0.f;
        }
        __syncthreads();
        #pragma unroll
        for (int k = 0; k < 16; k++) {
            float a[4], b[4];
            #pragma unroll
            for (int i = 0; i < 4; i++) a[i] = As[k][ty + 16*i];
            #pragma unroll
            for (int j = 0; j < 4; j++) b[j] = Bs[k][tx + 16*j];
            #pragma unroll
            for (int i = 0; i < 4; i++)
                #pragma unroll
                for (int j = 0; j < 4; j++) acc[i][j] += a[i]*b[j];
        }
        __syncthreads();
    }
    #pragma unroll
    for (int i = 0; i < 4; i++) {
        int r = row0 + ty + 16*i;
        if (r >= M) continue;
        #pragma unroll
        for (int j = 0; j < 4; j++) {
            int c = col0 + tx + 16*j;
            if (c >= N) continue;
            float v = acc[i][j] + bias[c];
            if (EPI == EPI_RES)  v += res[(size_t)r*N + c];
            if (EPI == EPI_GELU) v = 0.5f*v*(1.f + erff(v*0.70710678118654752f));
            C[(size_t)r*N + c] = v;
        }
    }
}

// ---------------- layernorm: one block (128 thr) per row of 384 --------------
__global__ void ln_k(const float* __restrict__ x, const float* __restrict__ g,
                     const float* __restrict__ b, float* __restrict__ y)
{
    int row = blockIdx.x;
    int tid = threadIdx.x;
    const float* xr = x + (size_t)row*D_;
    float v[3];
    float s = 0.f;
    #pragma unroll
    for (int i = 0; i < 3; i++) { v[i] = xr[tid + 128*i]; s += v[i]; }
    __shared__ float red[128];
    red[tid] = s; __syncthreads();
    for (int o = 64; o > 0; o >>= 1) { if (tid < o) red[tid] += red[tid+o]; __syncthreads(); }
    float mu = red[0] * (1.f/D_);
    __syncthreads();
    float s2 = 0.f;
    #pragma unroll
    for (int i = 0; i < 3; i++) { float d = v[i]-mu; s2 += d*d; }
    red[tid] = s2; __syncthreads();
    for (int o = 64; o > 0; o >>= 1) { if (tid < o) red[tid] += red[tid+o]; __syncthreads(); }
    float inv = rsqrtf(red[0]*(1.f/D_) + 1e-5f);
    float* yr = y + (size_t)row*D_;
    #pragma unroll
    for (int i = 0; i < 3; i++) { int c = tid + 128*i; yr[c] = (v[i]-mu)*inv*g[c] + b[c]; }
}

// ---------------- attention: block per (query, b*h) -------------------------
__global__ void attn_k(const float* __restrict__ qkv, float* __restrict__ out)
{
    int qi = blockIdx.x;              // 0..1024
    int bh = blockIdx.y;              // 0..47
    int b = bh / H_, h = bh % H_;
    const float* base = qkv + (size_t)b*SEQ_*QKV_N;
    __shared__ __align__(16) float qs[HD_];
    __shared__ float sc[SEQ_];
    __shared__ float red[128];
    __shared__ float obuf[HD_];
    int tid = threadIdx.x;            // 128
    if (tid < HD_) qs[tid] = base[(size_t)qi*QKV_N + h*HD_ + tid];
    __syncthreads();

    float lmax = -1e30f;
    const float4* qs4 = reinterpret_cast<const float4*>(qs);
    for (int j = tid; j < SEQ_; j += 128) {
        const float4* kr4 = reinterpret_cast<const float4*>(base + (size_t)j*QKV_N + D_ + h*HD_);
        float d = 0.f;
        #pragma unroll
        for (int e = 0; e < HD_/4; e++) {
            float4 kk = kr4[e]; float4 qq = qs4[e];
            d += qq.x*kk.x + qq.y*kk.y + qq.z*kk.z + qq.w*kk.w;
        }
        d *= 0.125f;
        sc[j] = d;
        lmax = fmaxf(lmax, d);
    }
    red[tid] = lmax; __syncthreads();
    for (int o = 64; o > 0; o >>= 1) { if (tid < o) red[tid] = fmaxf(red[tid], red[tid+o]); __syncthreads(); }
    float mx = red[0];
    __syncthreads();
    float ls = 0.f;
    for (int j = tid; j < SEQ_; j += 128) { float e = expf(sc[j]-mx); sc[j] = e; ls += e; }
    red[tid] = ls; __syncthreads();
    for (int o = 64; o > 0; o >>= 1) { if (tid < o) red[tid] += red[tid+o]; __syncthreads(); }
    float inv = 1.f / red[0];
    __syncthreads();

    int e = tid & 63, part = tid >> 6;     // two halves of key range
    float acc = 0.f;
    for (int j = part; j < SEQ_; j += 2)
        acc += sc[j] * base[(size_t)j*QKV_N + 2*D_ + h*HD_ + e];
    if (part == 1) obuf[e] = acc;
    __syncthreads();
    if (part == 0)
        out[((size_t)b*SEQ_ + qi)*D_ + h*HD_ + e] = (acc + obuf[e]) * inv;
}

// ---------------- patch-embed assemble: cls row + positional encoding --------
__global__ void assemble_k(const float* __restrict__ tmp, const float* __restrict__ cls,
                           float* __restrict__ x)
{
    int idx = blockIdx.x*blockDim.x + threadIdx.x;
    if (idx >= ROWS_*D_) return;
    int d = idx % D_;
    int rp = idx / D_;
    int pos = rp % SEQ_;
    int b = rp / SEQ_;
    float val = (pos == 0) ? cls[d] : tmp[((size_t)b*N_ + pos-1)*D_ + d];
    float expo = (float)(d & ~1) * (1.f/(float)D_);
    float ang = (float)pos / powf(10000.f, expo);
    float pe = (d & 1) ? cosf(ang) : sinf(ang);
    x[idx] = val + pe;
}

// ---------------- repack per-layer QKV weights into (D x 3D) K-major --------
__global__ void repack_k(const float* __restrict__ wq, const float* __restrict__ wk,
                         const float* __restrict__ wv, const float* __restrict__ bq,
                         const float* __restrict__ bk, const float* __restrict__ bv,
                         float* __restrict__ pw, float* __restrict__ pb)
{
    int idx = blockIdx.x*blockDim.x + threadIdx.x;
    if (idx >= L_*D_*QKV_N) return;
    int j = idx % QKV_N;
    int t = idx / QKV_N;
    int k = t % D_;
    int l = t / D_;
    int sec = j / D_, jj = j % D_, h = jj >> 6, e = jj & 63;
    const float* w = (sec == 0) ? wq : (sec == 1) ? wk : wv;
    pw[idx] = w[(((size_t)l*H_ + h)*D_ + k)*HD_ + e];
    if (k == 0) {
        const float* bb = (sec == 0) ? bq : (sec == 1) ? bk : bv;
        pb[l*QKV_N + j] = bb[((size_t)l*H_ + h)*HD_ + e];
    }
}

// ---------------- classifier logits (NC=2) ----------------------------------
__global__ void logits_k(const float* __restrict__ x, const float* __restrict__ cw,
                         const float* __restrict__ cb, float* __restrict__ lg)
{
    int idx = blockIdx.x*blockDim.x + threadIdx.x;
    if (idx >= B_*N_*NC_) return;
    int c = idx & 1;
    int bn = idx >> 1;
    int n = bn % N_, b = bn / N_;
    const float* xr = x + ((size_t)b*SEQ_ + n + 1)*D_;
    float s = cb[c];
    for (int d = 0; d < D_; d++) s += xr[d]*cw[d*NC_ + c];
    lg[idx] = s;
}

// ---------------- deconv-style upsample --------------------------------------
__global__ void up_k(const float* __restrict__ lg, const float* __restrict__ dw,
                     const float* __restrict__ db, float* __restrict__ out)
{
    int idx = blockIdx.x*blockDim.x + threadIdx.x;
    if (idx >= B_*NC_*N_*16*16) return;
    int ww = idx & 15;
    int t = idx >> 4;
    int hh = t & 15; t >>= 4;
    int n = t % N_;  t /= N_;
    int o = t & 1;   int b = t >> 1;
    float s = db[o];
    #pragma unroll
    for (int c = 0; c < NC_; c++)
        s += lg[((size_t)b*N_ + n)*NC_ + c] * dw[((c*NC_ + o)*16 + hh)*16 + ww];
    out[idx] = s;
}

// ---------------- launch ------------------------------------------------------
extern "C" void kernel_launch(void* const* d_in, const int* in_sizes, int n_in,
                              void* d_out, int out_size)
{
    const float* images  = (const float*)d_in[0];
    // d_in[1] = mask (unused by reference math)
    const float* patch_w = (const float*)d_in[2];
    const float* patch_b = (const float*)d_in[3];
    const float* cls_tok = (const float*)d_in[4];
    const float* ln1_g   = (const float*)d_in[5];
    const float* ln1_b   = (const float*)d_in[6];
    const float* wq      = (const float*)d_in[7];
    const float* bq      = (const float*)d_in[8];
    const float* wk      = (const float*)d_in[9];
    const float* bk      = (const float*)d_in[10];
    const float* wv      = (const float*)d_in[11];
    const float* bv      = (const float*)d_in[12];
    const float* wo      = (const float*)d_in[13];
    const float* bo      = (const float*)d_in[14];
    const float* ln2_g   = (const float*)d_in[15];
    const float* ln2_b   = (const float*)d_in[16];
    const float* w1      = (const float*)d_in[17];
    const float* b1      = (const float*)d_in[18];
    const float* w2      = (const float*)d_in[19];
    const float* b2      = (const float*)d_in[20];
    const float* cls_w   = (const float*)d_in[21];
    const float* cls_b   = (const float*)d_in[22];
    const float* dc_w    = (const float*)d_in[23];
    const float* dc_b    = (const float*)d_in[24];
    float* out = (float*)d_out;

    float *x, *hbuf, *qkv, *attn, *mlp, *pw, *pb, *lg;
    cudaGetSymbolAddress((void**)&x,    g_x);
    cudaGetSymbolAddress((void**)&hbuf, g_h);
    cudaGetSymbolAddress((void**)&qkv,  g_qkv);
    cudaGetSymbolAddress((void**)&attn, g_attn);
    cudaGetSymbolAddress((void**)&mlp,  g_mlp);
    cudaGetSymbolAddress((void**)&pw,   g_pw);
    cudaGetSymbolAddress((void**)&pb,   g_pb);
    cudaGetSymbolAddress((void**)&lg,   g_lg);

    // repack QKV weights/biases once
    repack_k<<<(L_*D_*QKV_N + 255)/256, 256>>>(wq, wk, wv, bq, bk, bv, pw, pb);

    // patch embed GEMM: (8192 x 256) @ (256 x 384) -> tmp (reuse g_mlp)
    {
        dim3 g((D_+63)/64, (B_*N_+63)/64);
        gemm_k<EPI_BIAS><<<g, 256>>>(images, patch_w, patch_b, nullptr, mlp,
                                     B_*N_, D_, 256);
    }
    assemble_k<<<(ROWS_*D_ + 255)/256, 256>>>(mlp, cls_tok, x);

    dim3 gq((QKV_N+63)/64, (ROWS_+63)/64);
    dim3 go((D_+63)/64,    (ROWS_+63)/64);
    dim3 g1((FF_+63)/64,   (ROWS_+63)/64);
    dim3 ga(SEQ_, B_*H_);

    for (int l = 0; l < L_; l++) {
        ln_k<<<ROWS_, 128>>>(x, ln1_g + l*D_, ln1_b + l*D_, hbuf);
        gemm_k<EPI_BIAS><<<gq, 256>>>(hbuf, pw + (size_t)l*D_*QKV_N, pb + l*QKV_N,
                                      nullptr, qkv, ROWS_, QKV_N, D_);
        attn_k<<<ga, 128>>>(qkv, attn);
        gemm_k<EPI_RES><<<go, 256>>>(attn, wo + (size_t)l*D_*D_, bo + l*D_,
                                     x, x, ROWS_, D_, D_);
        ln_k<<<ROWS_, 128>>>(x, ln2_g + l*D_, ln2_b + l*D_, hbuf);
        gemm_k<EPI_GELU><<<g1, 256>>>(hbuf, w1 + (size_t)l*D_*FF_, b1 + l*FF_,
                                      nullptr, mlp, ROWS_, FF_, D_);
        gemm_k<EPI_RES><<<go, 256>>>(mlp, w2 + (size_t)l*FF_*D_, b2 + l*D_,
                                     x, x, ROWS_, D_, FF_);
    }

    logits_k<<<(B_*N_*NC_ + 127)/128, 128>>>(x, cls_w, cls_b, lg);
    up_k<<<(B_*NC_*N_*256 + 255)/256, 256>>>(lg, dc_w, dc_b, out);
    (void)in_sizes; (void)n_in; (void)out_size;
}

// round 2
// speedup vs baseline: 1.9684x; 1.9684x over previous
#include <cuda_runtime.h>
#include <cuda_bf16.h>
#include <math.h>

// ---------------- problem constants ----------------
#define D_     384
#define H_     6
#define HD_    64
#define L_     4
#define B_     8
#define N_     1024
#define SEQ_   1025
#define ROWS_  (B_*SEQ_)     // 8200
#define NC_    2
#define QKV_N  (3*D_)        // 1152
#define FF_    (4*D_)        // 1536

typedef unsigned long long u64;
#define PACKF2(dst, lo, hi) asm("mov.b64 %0, {%1, %2};" : "=l"(dst) : "f"(lo), "f"(hi))
#define UNPACKF2(lo, hi, src) asm("mov.b64 {%0, %1}, %2;" : "=f"(lo), "=f"(hi) : "l"(src))
#define FMAF2(acc, a, b) asm("fma.rn.f32x2 %0, %1, %2, %0;" : "+l"(acc) : "l"(a), "l"(b))

// ---------------- scratch (device globals; no allocation allowed) ----------
__device__ float g_x[ROWS_*D_];
__device__ float g_h[ROWS_*D_];
__device__ float g_qkv[ROWS_*QKV_N];
__device__ float g_attn[ROWS_*D_];
__device__ float g_mlp[ROWS_*FF_];          // also reused as patch-embed tmp
__device__ float g_pw[L_*D_*QKV_N];
__device__ float g_pb[L_*QKV_N];
__device__ float g_lg[B_*N_*NC_];

// ---------------- GEMM: C = A(MxK) @ B(KxN) + bias (+res / gelu) ------------
// 128x128 tile, 256 threads, 8x8 micro-tile, double-buffered smem,
// packed f32x2 FMA. Requires N % 128 == 0, K % 16 == 0 (true for all calls).
#define EPI_BIAS 0
#define EPI_RES  1
#define EPI_GELU 2

template<int EPI>
__global__ __launch_bounds__(256)
void gemm2_k(const float* __restrict__ A, const float* __restrict__ Bm,
             const float* __restrict__ bias, const float* __restrict__ res,
             float* __restrict__ C, int M, int N, int K)
{
    __shared__ float As[2][16][132];   // [buf][k][m], pad 132 for STS + f4 align
    __shared__ float Bs[2][16][128];   // [buf][k][n]

    const int tid = threadIdx.x;
    const int tx = tid & 15, ty = tid >> 4;
    const int row0 = blockIdx.y * 128;
    const int col0 = blockIdx.x * 128;

    // global-load assignments
    const int arow = tid >> 2;            // 0..63 (and +64)
    const int akk  = (tid & 3) * 4;       // k chunk within 16
    const int bk   = tid >> 5;            // 0..7 (and +8)
    const int bcol = (tid & 31) * 4;      // 0..124

    u64 acc[4][8];
    #pragma unroll
    for (int p = 0; p < 4; p++)
        #pragma unroll
        for (int n = 0; n < 8; n++) acc[p][n] = 0ull;

    const int KT = K >> 4;
    float4 pa0, pa1, pb0, pb1;

    // prefetch tile 0
    {
        int r0 = row0 + arow, r1 = r0 + 64;
        pa0 = (r0 < M) ? *(const float4*)&A[(size_t)r0*K + akk] : make_float4(0.f,0.f,0.f,0.f);
        pa1 = (r1 < M) ? *(const float4*)&A[(size_t)r1*K + akk] : make_float4(0.f,0.f,0.f,0.f);
        pb0 = *(const float4*)&Bm[(size_t)bk*N     + col0 + bcol];
        pb1 = *(const float4*)&Bm[(size_t)(bk+8)*N + col0 + bcol];
    }
    // store tile 0
    {
        As[0][akk+0][arow] = pa0.x; As[0][akk+1][arow] = pa0.y;
        As[0][akk+2][arow] = pa0.z; As[0][akk+3][arow] = pa0.w;
        As[0][akk+0][arow+64] = pa1.x; As[0][akk+1][arow+64] = pa1.y;
        As[0][akk+2][arow+64] = pa1.z; As[0][akk+3][arow+64] = pa1.w;
        *(float4*)&Bs[0][bk][bcol]   = pb0;
        *(float4*)&Bs[0][bk+8][bcol] = pb1;
    }

    int buf = 0;
    for (int kt = 0; kt < KT; kt++) {
        __syncthreads();
        // prefetch next tile into registers
        if (kt + 1 < KT) {
            int k0 = (kt + 1) << 4;
            int r0 = row0 + arow, r1 = r0 + 64;
            pa0 = (r0 < M) ? *(const float4*)&A[(size_t)r0*K + k0 + akk] : make_float4(0.f,0.f,0.f,0.f);
            pa1 = (r1 < M) ? *(const float4*)&A[(size_t)r1*K + k0 + akk] : make_float4(0.f,0.f,0.f,0.f);
            pb0 = *(const float4*)&Bm[(size_t)(k0+bk)*N   + col0 + bcol];
            pb1 = *(const float4*)&Bm[(size_t)(k0+bk+8)*N + col0 + bcol];
        }
        // compute on current buffer
        #pragma unroll
        for (int k = 0; k < 16; k++) {
            float4 a0 = *(const float4*)&As[buf][k][ty*8];
            float4 a1 = *(const float4*)&As[buf][k][ty*8 + 4];
            float4 b0 = *(const float4*)&Bs[buf][k][tx*8];
            float4 b1 = *(const float4*)&Bs[buf][k][tx*8 + 4];
            u64 av[4], bv[8];
            PACKF2(av[0], a0.x, a0.y); PACKF2(av[1], a0.z, a0.w);
            PACKF2(av[2], a1.x, a1.y); PACKF2(av[3], a1.z, a1.w);
            PACKF2(bv[0], b0.x, b0.x); PACKF2(bv[1], b0.y, b0.y);
            PACKF2(bv[2], b0.z, b0.z); PACKF2(bv[3], b0.w, b0.w);
            PACKF2(bv[4], b1.x, b1.x); PACKF2(bv[5], b1.y, b1.y);
            PACKF2(bv[6], b1.z, b1.z); PACKF2(bv[7], b1.w, b1.w);
            #pragma unroll
            for (int p = 0; p < 4; p++)
                #pragma unroll
                for (int n = 0; n < 8; n++)
                    FMAF2(acc[p][n], av[p], bv[n]);
        }
        // store prefetched tile
        if (kt + 1 < KT) {
            int nb = buf ^ 1;
            As[nb][akk+0][arow] = pa0.x; As[nb][akk+1][arow] = pa0.y;
            As[nb][akk+2][arow] = pa0.z; As[nb][akk+3][arow] = pa0.w;
            As[nb][akk+0][arow+64] = pa1.x; As[nb][akk+1][arow+64] = pa1.y;
            As[nb][akk+2][arow+64] = pa1.z; As[nb][akk+3][arow+64] = pa1.w;
            *(float4*)&Bs[nb][bk][bcol]   = pb0;
            *(float4*)&Bs[nb][bk+8][bcol] = pb1;
        }
        buf ^= 1;
    }

    // epilogue
    #pragma unroll
    for (int p = 0; p < 4; p++) {
        float c0[8], c1[8];
        #pragma unroll
        for (int n = 0; n < 8; n++) UNPACKF2(c0[n], c1[n], acc[p][n]);
        #pragma unroll
        for (int s = 0; s < 2; s++) {
            int r = row0 + ty*8 + 2*p + s;
            if (r >= M) continue;
            const float* cr = s ? c1 : c0;
            #pragma unroll
            for (int n = 0; n < 8; n++) {
                int c = col0 + tx*8 + n;
                float v = cr[n] + bias[c];
                if (EPI == EPI_RES)  v += res[(size_t)r*N + c];
                if (EPI == EPI_GELU) v = 0.5f*v*(1.f + erff(v*0.70710678118654752f));
                C[(size_t)r*N + c] = v;
            }
        }
    }
}

// ---------------- layernorm: one block (128 thr) per row of 384 --------------
__global__ void ln_k(const float* __restrict__ x, const float* __restrict__ g,
                     const float* __restrict__ b, float* __restrict__ y)
{
    int row = blockIdx.x;
    int tid = threadIdx.x;
    const float* xr = x + (size_t)row*D_;
    float v[3];
    float s = 0.f;
    #pragma unroll
    for (int i = 0; i < 3; i++) { v[i] = xr[tid + 128*i]; s += v[i]; }
    __shared__ float red[128];
    red[tid] = s; __syncthreads();
    for (int o = 64; o > 0; o >>= 1) { if (tid < o) red[tid] += red[tid+o]; __syncthreads(); }
    float mu = red[0] * (1.f/D_);
    __syncthreads();
    float s2 = 0.f;
    #pragma unroll
    for (int i = 0; i < 3; i++) { float d = v[i]-mu; s2 += d*d; }
    red[tid] = s2; __syncthreads();
    for (int o = 64; o > 0; o >>= 1) { if (tid < o) red[tid] += red[tid+o]; __syncthreads(); }
    float inv = rsqrtf(red[0]*(1.f/D_) + 1e-5f);
    float* yr = y + (size_t)row*D_;
    #pragma unroll
    for (int i = 0; i < 3; i++) { int c = tid + 128*i; yr[c] = (v[i]-mu)*inv*g[c] + b[c]; }
}

// ---------------- attention v2: 8 queries per block, tiled K/V through smem --
__global__ __launch_bounds__(256, 2)
void attn2_k(const float* __restrict__ qkv, float* __restrict__ out)
{
    __shared__ float ss[8][1056];      // scores, padded (1025..1055 zeroed)
    __shared__ float Ks[32][65];       // K tile, reused as V tile
    const int tid  = threadIdx.x;
    const int w    = tid >> 5;         // warp = local query
    const int lane = tid & 31;
    const int bh = blockIdx.y;
    const int b = bh / H_, h = bh % H_;
    const int q0 = blockIdx.x * 8;
    const int qg = q0 + w;
    const float* base = qkv + (size_t)b*SEQ_*QKV_N;

    // this thread's query row into registers (all lanes of warp share q row)
    float qv[64];
    {
        int qc = (qg < SEQ_) ? qg : (SEQ_-1);
        const float4* qr = (const float4*)&base[(size_t)qc*QKV_N + h*HD_];
        #pragma unroll
        for (int e4 = 0; e4 < 16; e4++) {
            float4 t = qr[e4];
            qv[e4*4+0] = t.x; qv[e4*4+1] = t.y; qv[e4*4+2] = t.z; qv[e4*4+3] = t.w;
        }
    }

    // tile-load indices (32 rows x 64 cols, 8 floats per thread)
    const int jr = tid >> 3;
    const int e0 = (tid & 7) * 8;

    // ---- phase 1: scores ----
    for (int kb = 0; kb < SEQ_; kb += 32) {
        __syncthreads();
        int j = kb + jr;
        if (j < SEQ_) {
            const float4* kr = (const float4*)&base[(size_t)j*QKV_N + D_ + h*HD_ + e0];
            float4 v0 = kr[0], v1 = kr[1];
            Ks[jr][e0+0] = v0.x; Ks[jr][e0+1] = v0.y; Ks[jr][e0+2] = v0.z; Ks[jr][e0+3] = v0.w;
            Ks[jr][e0+4] = v1.x; Ks[jr][e0+5] = v1.y; Ks[jr][e0+6] = v1.z; Ks[jr][e0+7] = v1.w;
        } else {
            #pragma unroll
            for (int i = 0; i < 8; i++) Ks[jr][e0+i] = 0.f;
        }
        __syncthreads();
        int jj = kb + lane;
        float d = 0.f;
        #pragma unroll
        for (int e = 0; e < 64; e++) d += qv[e] * Ks[lane][e];
        if (jj < SEQ_) ss[w][jj] = d * 0.125f;
    }

    // ---- phase 2: softmax (per-warp, own row) ----
    float mx = -1e30f;
    for (int j = lane; j < SEQ_; j += 32) mx = fmaxf(mx, ss[w][j]);
    #pragma unroll
    for (int o = 16; o > 0; o >>= 1) mx = fmaxf(mx, __shfl_xor_sync(0xffffffffu, mx, o));
    float sum = 0.f;
    for (int j = lane; j < SEQ_; j += 32) {
        float e = expf(ss[w][j] - mx);
        ss[w][j] = e;
        sum += e;
    }
    #pragma unroll
    for (int o = 16; o > 0; o >>= 1) sum += __shfl_xor_sync(0xffffffffu, sum, o);
    float inv = 1.f / sum;
    if (lane > 0) ss[w][1024 + lane] = 0.f;   // pad 1025..1055
    __syncwarp();

    // ---- phase 3: attn @ V (reuse Ks as V tile) ----
    float o0 = 0.f, o1 = 0.f;
    for (int kb = 0; kb < SEQ_; kb += 32) {
        __syncthreads();
        int j = kb + jr;
        if (j < SEQ_) {
            const float4* vr = (const float4*)&base[(size_t)j*QKV_N + 2*D_ + h*HD_ + e0];
            float4 v0 = vr[0], v1 = vr[1];
            Ks[jr][e0+0] = v0.x; Ks[jr][e0+1] = v0.y; Ks[jr][e0+2] = v0.z; Ks[jr][e0+3] = v0.w;
            Ks[jr][e0+4] = v1.x; Ks[jr][e0+5] = v1.y; Ks[jr][e0+6] = v1.z; Ks[jr][e0+7] = v1.w;
        } else {
            #pragma unroll
            for (int i = 0; i < 8; i++) Ks[jr][e0+i] = 0.f;
        }
        __syncthreads();
        #pragma unroll
        for (int jj = 0; jj < 32; jj++) {
            float p = ss[w][kb + jj];
            o0 += p * Ks[jj][lane];
            o1 += p * Ks[jj][lane + 32];
        }
    }

    if (qg < SEQ_) {
        float* orow = &out[((size_t)b*SEQ_ + qg)*D_ + h*HD_];
        orow[lane]      = o0 * inv;
        orow[lane + 32] = o1 * inv;
    }
}

// ---------------- patch-embed assemble: cls row + positional encoding --------
__global__ void assemble_k(const float* __restrict__ tmp, const float* __restrict__ cls,
                           float* __restrict__ x)
{
    int idx = blockIdx.x*blockDim.x + threadIdx.x;
    if (idx >= ROWS_*D_) return;
    int d = idx % D_;
    int rp = idx / D_;
    int pos = rp % SEQ_;
    int b = rp / SEQ_;
    float val = (pos == 0) ? cls[d] : tmp[((size_t)b*N_ + pos-1)*D_ + d];
    float expo = (float)(d & ~1) * (1.f/(float)D_);
    float ang = (float)pos / powf(10000.f, expo);
    float pe = (d & 1) ? cosf(ang) : sinf(ang);
    x[idx] = val + pe;
}

// ---------------- repack per-layer QKV weights into (D x 3D) K-major --------
__global__ void repack_k(const float* __restrict__ wq, const float* __restrict__ wk,
                         const float* __restrict__ wv, const float* __restrict__ bq,
                         const float* __restrict__ bk, const float* __restrict__ bv,
                         float* __restrict__ pw, float* __restrict__ pb)
{
    int idx = blockIdx.x*blockDim.x + threadIdx.x;
    if (idx >= L_*D_*QKV_N) return;
    int j = idx % QKV_N;
    int t = idx / QKV_N;
    int k = t % D_;
    int l = t / D_;
    int sec = j / D_, jj = j % D_, h = jj >> 6, e = jj & 63;
    const float* w = (sec == 0) ? wq : (sec == 1) ? wk : wv;
    pw[idx] = w[(((size_t)l*H_ + h)*D_ + k)*HD_ + e];
    if (k == 0) {
        const float* bb = (sec == 0) ? bq : (sec == 1) ? bk : bv;
        pb[l*QKV_N + j] = bb[((size_t)l*H_ + h)*HD_ + e];
    }
}

// ---------------- classifier logits (NC=2) ----------------------------------
__global__ void logits_k(const float* __restrict__ x, const float* __restrict__ cw,
                         const float* __restrict__ cb, float* __restrict__ lg)
{
    int idx = blockIdx.x*blockDim.x + threadIdx.x;
    if (idx >= B_*N_*NC_) return;
    int c = idx & 1;
    int bn = idx >> 1;
    int n = bn % N_, b = bn / N_;
    const float4* xr = (const float4*)(x + ((size_t)b*SEQ_ + n + 1)*D_);
    float s = cb[c];
    #pragma unroll 4
    for (int d4 = 0; d4 < D_/4; d4++) {
        float4 xv = xr[d4];
        s += xv.x*cw[(d4*4+0)*NC_ + c] + xv.y*cw[(d4*4+1)*NC_ + c]
           + xv.z*cw[(d4*4+2)*NC_ + c] + xv.w*cw[(d4*4+3)*NC_ + c];
    }
    lg[idx] = s;
}

// ---------------- deconv-style upsample --------------------------------------
__global__ void up_k(const float* __restrict__ lg, const float* __restrict__ dw,
                     const float* __restrict__ db, float* __restrict__ out)
{
    int idx = blockIdx.x*blockDim.x + threadIdx.x;
    if (idx >= B_*NC_*N_*16*16) return;
    int ww = idx & 15;
    int t = idx >> 4;
    int hh = t & 15; t >>= 4;
    int n = t % N_;  t /= N_;
    int o = t & 1;   int b = t >> 1;
    float s = db[o];
    #pragma unroll
    for (int c = 0; c < NC_; c++)
        s += lg[((size_t)b*N_ + n)*NC_ + c] * dw[((c*NC_ + o)*16 + hh)*16 + ww];
    out[idx] = s;
}

// ---------------- launch ------------------------------------------------------
extern "C" void kernel_launch(void* const* d_in, const int* in_sizes, int n_in,
                              void* d_out, int out_size)
{
    const float* images  = (const float*)d_in[0];
    // d_in[1] = mask (unused by reference math)
    const float* patch_w = (const float*)d_in[2];
    const float* patch_b = (const float*)d_in[3];
    const float* cls_tok = (const float*)d_in[4];
    const float* ln1_g   = (const float*)d_in[5];
    const float* ln1_b   = (const float*)d_in[6];
    const float* wq      = (const float*)d_in[7];
    const float* bq      = (const float*)d_in[8];
    const float* wk      = (const float*)d_in[9];
    const float* bk      = (const float*)d_in[10];
    const float* wv      = (const float*)d_in[11];
    const float* bv      = (const float*)d_in[12];
    const float* wo      = (const float*)d_in[13];
    const float* bo      = (const float*)d_in[14];
    const float* ln2_g   = (const float*)d_in[15];
    const float* ln2_b   = (const float*)d_in[16];
    const float* w1      = (const float*)d_in[17];
    const float* b1      = (const float*)d_in[18];
    const float* w2      = (const float*)d_in[19];
    const float* b2      = (const float*)d_in[20];
    const float* cls_w   = (const float*)d_in[21];
    const float* cls_b   = (const float*)d_in[22];
    const float* dc_w    = (const float*)d_in[23];
    const float* dc_b    = (const float*)d_in[24];
    float* out = (float*)d_out;

    float *x, *hbuf, *qkv, *attn, *mlp, *pw, *pb, *lg;
    cudaGetSymbolAddress((void**)&x,    g_x);
    cudaGetSymbolAddress((void**)&hbuf, g_h);
    cudaGetSymbolAddress((void**)&qkv,  g_qkv);
    cudaGetSymbolAddress((void**)&attn, g_attn);
    cudaGetSymbolAddress((void**)&mlp,  g_mlp);
    cudaGetSymbolAddress((void**)&pw,   g_pw);
    cudaGetSymbolAddress((void**)&pb,   g_pb);
    cudaGetSymbolAddress((void**)&lg,   g_lg);

    // repack QKV weights/biases once
    repack_k<<<(L_*D_*QKV_N + 255)/256, 256>>>(wq, wk, wv, bq, bk, bv, pw, pb);

    // patch embed GEMM: (8192 x 256) @ (256 x 384) -> tmp (reuse g_mlp)
    {
        dim3 g(D_/128, (B_*N_)/128);
        gemm2_k<EPI_BIAS><<<g, 256>>>(images, patch_w, patch_b, nullptr, mlp,
                                      B_*N_, D_, 256);
    }
    assemble_k<<<(ROWS_*D_ + 255)/256, 256>>>(mlp, cls_tok, x);

    dim3 gq(QKV_N/128, (ROWS_+127)/128);
    dim3 go(D_/128,    (ROWS_+127)/128);
    dim3 g1(FF_/128,   (ROWS_+127)/128);
    dim3 ga((SEQ_+7)/8, B_*H_);

    for (int l = 0; l < L_; l++) {
        ln_k<<<ROWS_, 128>>>(x, ln1_g + l*D_, ln1_b + l*D_, hbuf);
        gemm2_k<EPI_BIAS><<<gq, 256>>>(hbuf, pw + (size_t)l*D_*QKV_N, pb + l*QKV_N,
                                       nullptr, qkv, ROWS_, QKV_N, D_);
        attn2_k<<<ga, 256>>>(qkv, attn);
        gemm2_k<EPI_RES><<<go, 256>>>(attn, wo + (size_t)l*D_*D_, bo + l*D_,
                                      x, x, ROWS_, D_, D_);
        ln_k<<<ROWS_, 128>>>(x, ln2_g + l*D_, ln2_b + l*D_, hbuf);
        gemm2_k<EPI_GELU><<<g1, 256>>>(hbuf, w1 + (size_t)l*D_*FF_, b1 + l*FF_,
                                       nullptr, mlp, ROWS_, FF_, D_);
        gemm2_k<EPI_RES><<<go, 256>>>(mlp, w2 + (size_t)l*FF_*D_, b2 + l*D_,
                                      x, x, ROWS_, D_, FF_);
    }

    logits_k<<<(B_*N_*NC_ + 127)/128, 128>>>(x, cls_w, cls_b, lg);
    up_k<<<(B_*NC_*N_*256 + 255)/256, 256>>>(lg, dc_w, dc_b, out);
    (void)in_sizes; (void)n_in; (void)out_size;
}

// round 3
// speedup vs baseline: 2.5616x; 1.3014x over previous
#include <cuda_runtime.h>
#include <cuda_bf16.h>
#include <math.h>

// ---------------- problem constants ----------------
#define D_     384
#define H_     6
#define HD_    64
#define L_     4
#define B_     8
#define N_     1024
#define SEQ_   1025
#define ROWS_  (B_*SEQ_)     // 8200
#define NC_    2
#define QKV_N  (3*D_)        // 1152
#define FF_    (4*D_)        // 1536

typedef unsigned long long u64;
typedef unsigned int u32;
#define PACKF2(dst, lo, hi) asm("mov.b64 %0, {%1, %2};" : "=l"(dst) : "f"(lo), "f"(hi))
#define UNPACKF2(lo, hi, src) asm("mov.b64 {%0, %1}, %2;" : "=f"(lo), "=f"(hi) : "l"(src))
#define FMAF2(acc, a, b) asm("fma.rn.f32x2 %0, %1, %2, %0;" : "+l"(acc) : "l"(a), "l"(b))

__device__ __forceinline__ float f2tf32(float f) {
    u32 u; asm("cvt.rna.tf32.f32 %0, %1;" : "=r"(u) : "f"(f));
    return __uint_as_float(u);
}

#define MMA_TF32(c, a, b) \
    asm("mma.sync.aligned.m16n8k8.row.col.f32.tf32.tf32.f32 " \
        "{%0,%1,%2,%3}, {%4,%5,%6,%7}, {%8,%9}, {%0,%1,%2,%3};" \
        : "+f"(c[0]), "+f"(c[1]), "+f"(c[2]), "+f"(c[3]) \
        : "r"(a[0]), "r"(a[1]), "r"(a[2]), "r"(a[3]), "r"(b[0]), "r"(b[1]))

// ---------------- scratch (device globals; no allocation allowed) ----------
__device__ float g_x[ROWS_*D_];
__device__ float g_h[ROWS_*D_];
__device__ float g_qkv[ROWS_*QKV_N];
__device__ float g_attn[ROWS_*D_];
__device__ float g_mlp[ROWS_*FF_];
__device__ float g_pw[L_*D_*QKV_N];
__device__ float g_pb[L_*QKV_N];
__device__ float g_lg[B_*N_*NC_];

// ---------------- GEMM (tf32 tensor-core): C = A@B + bias (+res/gelu) -------
// Block 128x128x32, 256 threads = 8 warps (2x4), warp tile 64x32 via
// 4x4 grid of m16n8k8 mma. Requires N%128==0, K%32==0.
#define EPI_BIAS 0
#define EPI_RES  1
#define EPI_GELU 2

template<int EPI>
__global__ __launch_bounds__(256)
void gemm3_k(const float* __restrict__ A, const float* __restrict__ Bm,
             const float* __restrict__ bias, const float* __restrict__ res,
             float* __restrict__ C, int M, int N, int K)
{
    __shared__ float As[128][36];   // [m][k], pad 36: frag banks group*4+tig
    __shared__ float Bs[32][136];   // [k][n], pad 136: frag banks tig*8+group

    const int tid  = threadIdx.x;
    const int lane = tid & 31;
    const int wid  = tid >> 5;
    const int wm   = (wid >> 2) * 64;    // warp m-origin in tile
    const int wn   = (wid & 3) * 32;     // warp n-origin in tile
    const int group = lane >> 2, tig = lane & 3;
    const int row0 = blockIdx.y * 128;
    const int col0 = blockIdx.x * 128;

    // loaders: A: thread -> row am, 4-float chunks at k = kk*8 + ak
    const int am = tid >> 1, ak = (tid & 1) * 4;
    // B: thread -> col chunk bn, rows bk + kk*8
    const int bn = (tid & 31) * 4, bk = tid >> 5;

    float c[4][4][4];
    #pragma unroll
    for (int i = 0; i < 4; i++)
        #pragma unroll
        for (int j = 0; j < 4; j++)
            #pragma unroll
            for (int f = 0; f < 4; f++) c[i][j][f] = 0.f;

    const int KT = K >> 5;
    float4 pa[4], pb[4];
    const bool arow_ok = (row0 + am) < M;

    // prefetch tile 0
    #pragma unroll
    for (int kk = 0; kk < 4; kk++) {
        pa[kk] = arow_ok ? *(const float4*)&A[(size_t)(row0+am)*K + kk*8 + ak]
                         : make_float4(0.f,0.f,0.f,0.f);
        pb[kk] = *(const float4*)&Bm[(size_t)(bk + kk*8)*N + col0 + bn];
    }

    for (int kt = 0; kt < KT; kt++) {
        // store current regs -> smem (with tf32 rounding)
        #pragma unroll
        for (int kk = 0; kk < 4; kk++) {
            float4 t = pa[kk];
            t.x = f2tf32(t.x); t.y = f2tf32(t.y); t.z = f2tf32(t.z); t.w = f2tf32(t.w);
            *(float4*)&As[am][kk*8 + ak] = t;
            float4 u = pb[kk];
            u.x = f2tf32(u.x); u.y = f2tf32(u.y); u.z = f2tf32(u.z); u.w = f2tf32(u.w);
            *(float4*)&Bs[bk + kk*8][bn] = u;
        }
        __syncthreads();

        // prefetch next tile
        if (kt + 1 < KT) {
            int k0 = (kt + 1) << 5;
            #pragma unroll
            for (int kk = 0; kk < 4; kk++) {
                pa[kk] = arow_ok ? *(const float4*)&A[(size_t)(row0+am)*K + k0 + kk*8 + ak]
                                 : make_float4(0.f,0.f,0.f,0.f);
                pb[kk] = *(const float4*)&Bm[(size_t)(k0 + bk + kk*8)*N + col0 + bn];
            }
        }

        // compute: 4 k-steps of 8
        #pragma unroll
        for (int ks = 0; ks < 4; ks++) {
            const int k8 = ks * 8;
            u32 a[4][4], b[4][2];
            #pragma unroll
            for (int i = 0; i < 4; i++) {
                int m0 = wm + 16*i;
                a[i][0] = __float_as_uint(As[m0 + group    ][k8 + tig    ]);
                a[i][1] = __float_as_uint(As[m0 + group + 8][k8 + tig    ]);
                a[i][2] = __float_as_uint(As[m0 + group    ][k8 + tig + 4]);
                a[i][3] = __float_as_uint(As[m0 + group + 8][k8 + tig + 4]);
            }
            #pragma unroll
            for (int j = 0; j < 4; j++) {
                int n0 = wn + 8*j;
                b[j][0] = __float_as_uint(Bs[k8 + tig    ][n0 + group]);
                b[j][1] = __float_as_uint(Bs[k8 + tig + 4][n0 + group]);
            }
            #pragma unroll
            for (int i = 0; i < 4; i++)
                #pragma unroll
                for (int j = 0; j < 4; j++)
                    MMA_TF32(c[i][j], a[i], b[j]);
        }
        __syncthreads();
    }

    // epilogue: each thread owns (rows r0,r0+8) x (cols cb,cb+1) per (i,j)
    #pragma unroll
    for (int i = 0; i < 4; i++) {
        int r0 = row0 + wm + 16*i + group;
        int r1 = r0 + 8;
        #pragma unroll
        for (int j = 0; j < 4; j++) {
            int cb = col0 + wn + 8*j + 2*tig;
            float b0 = bias[cb], b1 = bias[cb+1];
            if (r0 < M) {
                float v0 = c[i][j][0] + b0, v1 = c[i][j][1] + b1;
                if (EPI == EPI_RES) { v0 += res[(size_t)r0*N+cb]; v1 += res[(size_t)r0*N+cb+1]; }
                if (EPI == EPI_GELU) {
                    v0 = 0.5f*v0*(1.f + erff(v0*0.70710678118654752f));
                    v1 = 0.5f*v1*(1.f + erff(v1*0.70710678118654752f));
                }
                *(float2*)&C[(size_t)r0*N + cb] = make_float2(v0, v1);
            }
            if (r1 < M) {
                float v0 = c[i][j][2] + b0, v1 = c[i][j][3] + b1;
                if (EPI == EPI_RES) { v0 += res[(size_t)r1*N+cb]; v1 += res[(size_t)r1*N+cb+1]; }
                if (EPI == EPI_GELU) {
                    v0 = 0.5f*v0*(1.f + erff(v0*0.70710678118654752f));
                    v1 = 0.5f*v1*(1.f + erff(v1*0.70710678118654752f));
                }
                *(float2*)&C[(size_t)r1*N + cb] = make_float2(v0, v1);
            }
        }
    }
}

// ---------------- layernorm ---------------------------------------------------
__global__ void ln_k(const float* __restrict__ x, const float* __restrict__ g,
                     const float* __restrict__ b, float* __restrict__ y)
{
    int row = blockIdx.x;
    int tid = threadIdx.x;
    const float* xr = x + (size_t)row*D_;
    float v[3];
    float s = 0.f;
    #pragma unroll
    for (int i = 0; i < 3; i++) { v[i] = xr[tid + 128*i]; s += v[i]; }
    __shared__ float red[128];
    red[tid] = s; __syncthreads();
    for (int o = 64; o > 0; o >>= 1) { if (tid < o) red[tid] += red[tid+o]; __syncthreads(); }
    float mu = red[0] * (1.f/D_);
    __syncthreads();
    float s2 = 0.f;
    #pragma unroll
    for (int i = 0; i < 3; i++) { float d = v[i]-mu; s2 += d*d; }
    red[tid] = s2; __syncthreads();
    for (int o = 64; o > 0; o >>= 1) { if (tid < o) red[tid] += red[tid+o]; __syncthreads(); }
    float inv = rsqrtf(red[0]*(1.f/D_) + 1e-5f);
    float* yr = y + (size_t)row*D_;
    #pragma unroll
    for (int i = 0; i < 3; i++) { int c = tid + 128*i; yr[c] = (v[i]-mu)*inv*g[c] + b[c]; }
}

// ---------------- attention: 8 queries/block, f32x2-packed phases ------------
__global__ __launch_bounds__(256, 2)
void attn3_k(const float* __restrict__ qkv, float* __restrict__ out)
{
    __shared__ float ss[8][1056];      // scores; 1025..1055 zeroed
    __shared__ float Ks[32][68];       // K tile / V tile (stride 68: 8B-aligned rows)
    const int tid  = threadIdx.x;
    const int w    = tid >> 5;         // warp = local query
    const int lane = tid & 31;
    const int bh = blockIdx.y;
    const int b = bh / H_, h = bh % H_;
    const int qg = blockIdx.x * 8 + w;
    const float* base = qkv + (size_t)b*SEQ_*QKV_N;

    // query row packed into 32 f32x2 registers
    u64 qv2[32];
    {
        int qc = (qg < SEQ_) ? qg : (SEQ_-1);
        const float4* qr = (const float4*)&base[(size_t)qc*QKV_N + h*HD_];
        #pragma unroll
        for (int e4 = 0; e4 < 16; e4++) {
            float4 t = qr[e4];
            PACKF2(qv2[e4*2+0], t.x, t.y);
            PACKF2(qv2[e4*2+1], t.z, t.w);
        }
    }

    const int jr = tid >> 3;           // tile row 0..31
    const int e0 = (tid & 7) * 8;      // col chunk

    // ---- phase 1: scores ----
    for (int kb = 0; kb < SEQ_; kb += 32) {
        __syncthreads();
        int j = kb + jr;
        if (j < SEQ_) {
            const float4* kr = (const float4*)&base[(size_t)j*QKV_N + D_ + h*HD_ + e0];
            *(float4*)&Ks[jr][e0]   = kr[0];
            *(float4*)&Ks[jr][e0+4] = kr[1];
        } else {
            *(float4*)&Ks[jr][e0]   = make_float4(0.f,0.f,0.f,0.f);
            *(float4*)&Ks[jr][e0+4] = make_float4(0.f,0.f,0.f,0.f);
        }
        __syncthreads();
        int jj = kb + lane;
        u64 acc2 = 0ull;
        const u64* kr2 = (const u64*)&Ks[lane][0];
        #pragma unroll
        for (int e2 = 0; e2 < 32; e2++) FMAF2(acc2, qv2[e2], kr2[e2]);
        float lo, hi; UNPACKF2(lo, hi, acc2);
        if (jj < SEQ_) ss[w][jj] = (lo + hi) * 0.125f;
    }

    // ---- phase 2: softmax (per-warp row) ----
    float mx = -1e30f;
    for (int j = lane; j < SEQ_; j += 32) mx = fmaxf(mx, ss[w][j]);
    #pragma unroll
    for (int o = 16; o > 0; o >>= 1) mx = fmaxf(mx, __shfl_xor_sync(0xffffffffu, mx, o));
    float sum = 0.f;
    for (int j = lane; j < SEQ_; j += 32) {
        float e = __expf(ss[w][j] - mx);
        ss[w][j] = e;
        sum += e;
    }
    #pragma unroll
    for (int o = 16; o > 0; o >>= 1) sum += __shfl_xor_sync(0xffffffffu, sum, o);
    float inv = 1.f / sum;
    if (lane > 0) ss[w][1024 + lane] = 0.f;   // pad 1025..1055
    __syncwarp();

    // ---- phase 3: attn @ V ----
    u64 o2 = 0ull;
    for (int kb = 0; kb < SEQ_; kb += 32) {
        __syncthreads();
        int j = kb + jr;
        if (j < SEQ_) {
            const float4* vr = (const float4*)&base[(size_t)j*QKV_N + 2*D_ + h*HD_ + e0];
            *(float4*)&Ks[jr][e0]   = vr[0];
            *(float4*)&Ks[jr][e0+4] = vr[1];
        } else {
            *(float4*)&Ks[jr][e0]   = make_float4(0.f,0.f,0.f,0.f);
            *(float4*)&Ks[jr][e0+4] = make_float4(0.f,0.f,0.f,0.f);
        }
        __syncthreads();
        #pragma unroll
        for (int jj = 0; jj < 32; jj++) {
            float p = ss[w][kb + jj];
            u64 p2; PACKF2(p2, p, p);
            u64 v2 = *(const u64*)&Ks[jj][2*lane];
            FMAF2(o2, p2, v2);
        }
    }

    if (qg < SEQ_) {
        float lo, hi; UNPACKF2(lo, hi, o2);
        float* orow = &out[((size_t)b*SEQ_ + qg)*D_ + h*HD_];
        *(float2*)&orow[2*lane] = make_float2(lo * inv, hi * inv);
    }
}

// ---------------- patch-embed assemble ---------------------------------------
__global__ void assemble_k(const float* __restrict__ tmp, const float* __restrict__ cls,
                           float* __restrict__ x)
{
    int idx = blockIdx.x*blockDim.x + threadIdx.x;
    if (idx >= ROWS_*D_) return;
    int d = idx % D_;
    int rp = idx / D_;
    int pos = rp % SEQ_;
    int b = rp / SEQ_;
    float val = (pos == 0) ? cls[d] : tmp[((size_t)b*N_ + pos-1)*D_ + d];
    float expo = (float)(d & ~1) * (1.f/(float)D_);
    float ang = (float)pos / powf(10000.f, expo);
    float pe = (d & 1) ? cosf(ang) : sinf(ang);
    x[idx] = val + pe;
}

// ---------------- repack QKV weights -----------------------------------------
__global__ void repack_k(const float* __restrict__ wq, const float* __restrict__ wk,
                         const float* __restrict__ wv, const float* __restrict__ bq,
                         const float* __restrict__ bk, const float* __restrict__ bv,
                         float* __restrict__ pw, float* __restrict__ pb)
{
    int idx = blockIdx.x*blockDim.x + threadIdx.x;
    if (idx >= L_*D_*QKV_N) return;
    int j = idx % QKV_N;
    int t = idx / QKV_N;
    int k = t % D_;
    int l = t / D_;
    int sec = j / D_, jj = j % D_, h = jj >> 6, e = jj & 63;
    const float* w = (sec == 0) ? wq : (sec == 1) ? wk : wv;
    pw[idx] = w[(((size_t)l*H_ + h)*D_ + k)*HD_ + e];
    if (k == 0) {
        const float* bb = (sec == 0) ? bq : (sec == 1) ? bk : bv;
        pb[l*QKV_N + j] = bb[((size_t)l*H_ + h)*HD_ + e];
    }
}

// ---------------- classifier logits (NC=2) -----------------------------------
__global__ void logits_k(const float* __restrict__ x, const float* __restrict__ cw,
                         const float* __restrict__ cb, float* __restrict__ lg)
{
    int idx = blockIdx.x*blockDim.x + threadIdx.x;
    if (idx >= B_*N_*NC_) return;
    int c = idx & 1;
    int bn = idx >> 1;
    int n = bn % N_, b = bn / N_;
    const float4* xr = (const float4*)(x + ((size_t)b*SEQ_ + n + 1)*D_);
    float s = cb[c];
    #pragma unroll 4
    for (int d4 = 0; d4 < D_/4; d4++) {
        float4 xv = xr[d4];
        s += xv.x*cw[(d4*4+0)*NC_ + c] + xv.y*cw[(d4*4+1)*NC_ + c]
           + xv.z*cw[(d4*4+2)*NC_ + c] + xv.w*cw[(d4*4+3)*NC_ + c];
    }
    lg[idx] = s;
}

// ---------------- deconv upsample ---------------------------------------------
__global__ void up_k(const float* __restrict__ lg, const float* __restrict__ dw,
                     const float* __restrict__ db, float* __restrict__ out)
{
    int idx = blockIdx.x*blockDim.x + threadIdx.x;
    if (idx >= B_*NC_*N_*16*16) return;
    int ww = idx & 15;
    int t = idx >> 4;
    int hh = t & 15; t >>= 4;
    int n = t % N_;  t /= N_;
    int o = t & 1;   int b = t >> 1;
    float s = db[o];
    #pragma unroll
    for (int c = 0; c < NC_; c++)
        s += lg[((size_t)b*N_ + n)*NC_ + c] * dw[((c*NC_ + o)*16 + hh)*16 + ww];
    out[idx] = s;
}

// ---------------- launch ------------------------------------------------------
extern "C" void kernel_launch(void* const* d_in, const int* in_sizes, int n_in,
                              void* d_out, int out_size)
{
    const float* images  = (const float*)d_in[0];
    const float* patch_w = (const float*)d_in[2];
    const float* patch_b = (const float*)d_in[3];
    const float* cls_tok = (const float*)d_in[4];
    const float* ln1_g   = (const float*)d_in[5];
    const float* ln1_b   = (const float*)d_in[6];
    const float* wq      = (const float*)d_in[7];
    const float* bq      = (const float*)d_in[8];
    const float* wk      = (const float*)d_in[9];
    const float* bk      = (const float*)d_in[10];
    const float* wv      = (const float*)d_in[11];
    const float* bv      = (const float*)d_in[12];
    const float* wo      = (const float*)d_in[13];
    const float* bo      = (const float*)d_in[14];
    const float* ln2_g   = (const float*)d_in[15];
    const float* ln2_b   = (const float*)d_in[16];
    const float* w1      = (const float*)d_in[17];
    const float* b1      = (const float*)d_in[18];
    const float* w2      = (const float*)d_in[19];
    const float* b2      = (const float*)d_in[20];
    const float* cls_w   = (const float*)d_in[21];
    const float* cls_b   = (const float*)d_in[22];
    const float* dc_w    = (const float*)d_in[23];
    const float* dc_b    = (const float*)d_in[24];
    float* out = (float*)d_out;

    float *x, *hbuf, *qkv, *attn, *mlp, *pw, *pb, *lg;
    cudaGetSymbolAddress((void**)&x,    g_x);
    cudaGetSymbolAddress((void**)&hbuf, g_h);
    cudaGetSymbolAddress((void**)&qkv,  g_qkv);
    cudaGetSymbolAddress((void**)&attn, g_attn);
    cudaGetSymbolAddress((void**)&mlp,  g_mlp);
    cudaGetSymbolAddress((void**)&pw,   g_pw);
    cudaGetSymbolAddress((void**)&pb,   g_pb);
    cudaGetSymbolAddress((void**)&lg,   g_lg);

    repack_k<<<(L_*D_*QKV_N + 255)/256, 256>>>(wq, wk, wv, bq, bk, bv, pw, pb);

    // patch embed: (8192 x 256) @ (256 x 384)
    {
        dim3 g(D_/128, (B_*N_)/128);
        gemm3_k<EPI_BIAS><<<g, 256>>>(images, patch_w, patch_b, nullptr, mlp,
                                      B_*N_, D_, 256);
    }
    assemble_k<<<(ROWS_*D_ + 255)/256, 256>>>(mlp, cls_tok, x);

    dim3 gq(QKV_N/128, (ROWS_+127)/128);
    dim3 go(D_/128,    (ROWS_+127)/128);
    dim3 g1(FF_/128,   (ROWS_+127)/128);
    dim3 ga((SEQ_+7)/8, B_*H_);

    for (int l = 0; l < L_; l++) {
        ln_k<<<ROWS_, 128>>>(x, ln1_g + l*D_, ln1_b + l*D_, hbuf);
        gemm3_k<EPI_BIAS><<<gq, 256>>>(hbuf, pw + (size_t)l*D_*QKV_N, pb + l*QKV_N,
                                       nullptr, qkv, ROWS_, QKV_N, D_);
        attn3_k<<<ga, 256>>>(qkv, attn);
        gemm3_k<EPI_RES><<<go, 256>>>(attn, wo + (size_t)l*D_*D_, bo + l*D_,
                                      x, x, ROWS_, D_, D_);
        ln_k<<<ROWS_, 128>>>(x, ln2_g + l*D_, ln2_b + l*D_, hbuf);
        gemm3_k<EPI_GELU><<<g1, 256>>>(hbuf, w1 + (size_t)l*D_*FF_, b1 + l*FF_,
                                       nullptr, mlp, ROWS_, FF_, D_);
        gemm3_k<EPI_RES><<<go, 256>>>(mlp, w2 + (size_t)l*FF_*D_, b2 + l*D_,
                                      x, x, ROWS_, D_, FF_);
    }

    logits_k<<<(B_*N_*NC_ + 127)/128, 128>>>(x, cls_w, cls_b, lg);
    up_k<<<(B_*NC_*N_*256 + 255)/256, 256>>>(lg, dc_w, dc_b, out);
    (void)in_sizes; (void)n_in; (void)out_size;
}

// round 5
// speedup vs baseline: 2.9323x; 1.1447x over previous
#include <cuda_runtime.h>
#include <cuda_bf16.h>
#include <math.h>
#include <stdint.h>

// ---------------- problem constants ----------------
#define D_     384
#define H_     6
#define HD_    64
#define L_     4
#define B_     8
#define N_     1024
#define SEQ_   1025
#define ROWS_  (B_*SEQ_)     // 8200
#define ROWSP_ 8320          // padded to 65*128 -> no M predicates in GEMM
#define NC_    2
#define QKV_N  (3*D_)        // 1152
#define FF_    (4*D_)        // 1536

typedef unsigned long long u64;
typedef unsigned int u32;

#define PACKF2(dst, lo, hi) asm("mov.b64 %0, {%1, %2};" : "=l"(dst) : "f"(lo), "f"(hi))
#define UNPACKF2(lo, hi, src) asm("mov.b64 {%0, %1}, %2;" : "=f"(lo), "=f"(hi) : "l"(src))
#define FMAF2(acc, a, b) asm("fma.rn.f32x2 %0, %1, %2, %0;" : "+l"(acc) : "l"(a), "l"(b))

__device__ __forceinline__ float f2tf32(float f) {
    u32 u; asm("cvt.rna.tf32.f32 %0, %1;" : "=r"(u) : "f"(f));
    return __uint_as_float(u);
}

#define MMA_TF32(c, a, b) \
    asm("mma.sync.aligned.m16n8k8.row.col.f32.tf32.tf32.f32 " \
        "{%0,%1,%2,%3}, {%4,%5,%6,%7}, {%8,%9}, {%0,%1,%2,%3};" \
        : "+f"(c[0]), "+f"(c[1]), "+f"(c[2]), "+f"(c[3]) \
        : "r"(a[0]), "r"(a[1]), "r"(a[2]), "r"(a[3]), "r"(b[0]), "r"(b[1]))

#define CP16(saddr, gptr) \
    asm volatile("cp.async.ca.shared.global [%0], [%1], 16;" :: "r"(saddr), "l"(gptr))
#define CP_COMMIT() asm volatile("cp.async.commit_group;" ::: "memory")
#define CP_WAIT0()  asm volatile("cp.async.wait_group 0;" ::: "memory")

__device__ __forceinline__ u32 smem_u32(const void* p) {
    u32 a;
    asm("{ .reg .u64 t; cvta.to.shared.u64 t, %1; cvt.u32.u64 %0, t; }" : "=r"(a) : "l"(p));
    return a;
}

// ---------------- scratch (device globals; no allocation allowed) ----------
__device__ float g_x[ROWSP_*D_];        // residual (fp32)
__device__ float g_h[ROWSP_*D_];        // ln out (tf32-rounded); pad rows stay 0
__device__ float g_qkv[ROWSP_*QKV_N];   // qkv (fp32); also patch-embed tmp
__device__ float g_attn[ROWSP_*D_];     // attn out (tf32-rounded); pad rows stay 0
__device__ float g_mlp[ROWSP_*FF_];     // gelu out (tf32-rounded)
__device__ float g_pw[L_*D_*QKV_N];
__device__ float g_pb[L_*QKV_N];
__device__ float g_qkvT[L_*QKV_N*D_];   // [l][n][k] tf32-rounded
__device__ float g_woT[L_*D_*D_];
__device__ float g_w1T[L_*FF_*D_];
__device__ float g_w2T[L_*D_*FF_];
__device__ float g_patT[D_*256];
__device__ float g_img[B_*N_*256];      // images tf32-rounded
__device__ float g_lg[B_*N_*NC_];

// ---------------- GEMM v4 (tf32 mma, 64x64 warp tiles, cp.async) -------------
// C[M,N] = A[M,K] @ B[N,K]^T + bias (+res / gelu). M%128==0 (padded),
// N%128==0, K%32==0. A,B pre-rounded to tf32.
#define EPI_BIAS 0
#define EPI_RES  1
#define EPI_GELU 2
#define SSTRIDE 36
#define SBUF    (128*SSTRIDE)          // floats per stage per operand

__device__ __forceinline__ float gelu_f(float v) {
    return 0.5f * v * (1.f + erff(v * 0.70710678118654752f));
}

template<int EPI>
__global__ __launch_bounds__(128, 2)
void gemm4_k(const float* __restrict__ A, const float* __restrict__ Bm,
             const float* __restrict__ bias, const float* __restrict__ res,
             float* __restrict__ C, int M, int N, int K)
{
    extern __shared__ float sm[];
    // layout: As0 | As1 | Bs0 | Bs1, each SBUF floats
    const int tid  = threadIdx.x;
    const int lane = tid & 31, wid = tid >> 5;
    const int wm = (wid >> 1) * 64, wn = (wid & 1) * 64;
    const int g = lane >> 2, t = lane & 3;
    const size_t row0 = (size_t)blockIdx.y * 128;
    const size_t col0 = (size_t)blockIdx.x * 128;

    const int lr = tid >> 3;            // 0..15, +16 per it
    const int lk = (tid & 7) * 4;       // 16B k-chunk

    const float* Aptr = A + (row0 + lr) * K + lk;
    const float* Bptr = Bm + (col0 + lr) * K + lk;
    const u32 asb0 = smem_u32(sm);
    const u32 dst_off = (u32)(lr * SSTRIDE + lk) * 4;

    float c[4][8][4];
    #pragma unroll
    for (int i = 0; i < 4; i++)
        #pragma unroll
        for (int j = 0; j < 8; j++)
            #pragma unroll
            for (int f = 0; f < 4; f++) c[i][j][f] = 0.f;

    const int KT = K >> 5;

    // prologue: stage 0
    {
        u32 ad = asb0 + dst_off;
        u32 bd = asb0 + 2*SBUF*4 + dst_off;
        #pragma unroll
        for (int it = 0; it < 8; it++) {
            CP16(ad + it*16*SSTRIDE*4, Aptr + (size_t)it*16*K);
            CP16(bd + it*16*SSTRIDE*4, Bptr + (size_t)it*16*K);
        }
        CP_COMMIT();
    }

    int buf = 0;
    for (int kt = 0; kt < KT; kt++) {
        CP_WAIT0();
        __syncthreads();
        if (kt + 1 < KT) {
            int k0 = (kt + 1) << 5;
            u32 ad = asb0 + (buf^1)*SBUF*4 + dst_off;
            u32 bd = asb0 + (2 + (buf^1))*SBUF*4 + dst_off;
            #pragma unroll
            for (int it = 0; it < 8; it++) {
                CP16(ad + it*16*SSTRIDE*4, Aptr + k0 + (size_t)it*16*K);
                CP16(bd + it*16*SSTRIDE*4, Bptr + k0 + (size_t)it*16*K);
            }
            CP_COMMIT();
        }
        const float* As_ = sm + buf*SBUF;
        const float* Bs_ = sm + (2 + buf)*SBUF;
        #pragma unroll
        for (int ks = 0; ks < 4; ks++) {
            const int k8 = ks * 8;
            u32 a[4][4], b[8][2];
            #pragma unroll
            for (int i = 0; i < 4; i++) {
                int m0 = wm + 16*i;
                a[i][0] = __float_as_uint(As_[(m0+g  )*SSTRIDE + k8 + t  ]);
                a[i][1] = __float_as_uint(As_[(m0+g+8)*SSTRIDE + k8 + t  ]);
                a[i][2] = __float_as_uint(As_[(m0+g  )*SSTRIDE + k8 + t+4]);
                a[i][3] = __float_as_uint(As_[(m0+g+8)*SSTRIDE + k8 + t+4]);
            }
            #pragma unroll
            for (int j = 0; j < 8; j++) {
                int n0 = wn + 8*j;
                b[j][0] = __float_as_uint(Bs_[(n0+g)*SSTRIDE + k8 + t  ]);
                b[j][1] = __float_as_uint(Bs_[(n0+g)*SSTRIDE + k8 + t+4]);
            }
            #pragma unroll
            for (int i = 0; i < 4; i++)
                #pragma unroll
                for (int j = 0; j < 8; j++)
                    MMA_TF32(c[i][j], a[i], b[j]);
        }
        __syncthreads();
        buf ^= 1;
    }

    // epilogue
    #pragma unroll
    for (int i = 0; i < 4; i++) {
        size_t r0 = row0 + wm + 16*i + g;
        size_t r1 = r0 + 8;
        #pragma unroll
        for (int j = 0; j < 8; j++) {
            int cb = (int)col0 + wn + 8*j + 2*t;
            float b0 = bias[cb], b1 = bias[cb+1];
            float v0 = c[i][j][0] + b0, v1 = c[i][j][1] + b1;
            float v2 = c[i][j][2] + b0, v3 = c[i][j][3] + b1;
            if (EPI == EPI_RES) {
                float2 ra = *(const float2*)&res[r0*N + cb];
                float2 rb = *(const float2*)&res[r1*N + cb];
                v0 += ra.x; v1 += ra.y; v2 += rb.x; v3 += rb.y;
            }
            if (EPI == EPI_GELU) {
                v0 = f2tf32(gelu_f(v0)); v1 = f2tf32(gelu_f(v1));
                v2 = f2tf32(gelu_f(v2)); v3 = f2tf32(gelu_f(v3));
            }
            *(float2*)&C[r0*N + cb] = make_float2(v0, v1);
            *(float2*)&C[r1*N + cb] = make_float2(v2, v3);
        }
    }
}

// ---------------- layernorm: emits tf32-rounded fp32 -------------------------
__global__ void ln_k(const float* __restrict__ x, const float* __restrict__ g,
                     const float* __restrict__ b, float* __restrict__ y)
{
    int row = blockIdx.x;
    int tid = threadIdx.x;
    const float* xr = x + (size_t)row*D_;
    float v[3];
    float s = 0.f;
    #pragma unroll
    for (int i = 0; i < 3; i++) { v[i] = xr[tid + 128*i]; s += v[i]; }
    __shared__ float red[128];
    red[tid] = s; __syncthreads();
    for (int o = 64; o > 0; o >>= 1) { if (tid < o) red[tid] += red[tid+o]; __syncthreads(); }
    float mu = red[0] * (1.f/D_);
    __syncthreads();
    float s2 = 0.f;
    #pragma unroll
    for (int i = 0; i < 3; i++) { float d = v[i]-mu; s2 += d*d; }
    red[tid] = s2; __syncthreads();
    for (int o = 64; o > 0; o >>= 1) { if (tid < o) red[tid] += red[tid+o]; __syncthreads(); }
    float inv = rsqrtf(red[0]*(1.f/D_) + 1e-5f);
    float* yr = y + (size_t)row*D_;
    #pragma unroll
    for (int i = 0; i < 3; i++) {
        int c = tid + 128*i;
        yr[c] = f2tf32((v[i]-mu)*inv*g[c] + b[c]);
    }
}

// ---------------- attention: 8 queries/block (emits tf32-rounded) ------------
__global__ __launch_bounds__(256, 2)
void attn3_k(const float* __restrict__ qkv, float* __restrict__ out)
{
    __shared__ float ss[8][1056];
    __shared__ float Ks[32][68];
    const int tid  = threadIdx.x;
    const int w    = tid >> 5;
    const int lane = tid & 31;
    const int bh = blockIdx.y;
    const int b = bh / H_, h = bh % H_;
    const int qg = blockIdx.x * 8 + w;
    const float* base = qkv + (size_t)b*SEQ_*QKV_N;

    u64 qv2[32];
    {
        int qc = (qg < SEQ_) ? qg : (SEQ_-1);
        const float4* qr = (const float4*)&base[(size_t)qc*QKV_N + h*HD_];
        #pragma unroll
        for (int e4 = 0; e4 < 16; e4++) {
            float4 t = qr[e4];
            PACKF2(qv2[e4*2+0], t.x, t.y);
            PACKF2(qv2[e4*2+1], t.z, t.w);
        }
    }

    const int jr = tid >> 3;
    const int e0 = (tid & 7) * 8;

    for (int kb = 0; kb < SEQ_; kb += 32) {
        __syncthreads();
        int j = kb + jr;
        if (j < SEQ_) {
            const float4* kr = (const float4*)&base[(size_t)j*QKV_N + D_ + h*HD_ + e0];
            *(float4*)&Ks[jr][e0]   = kr[0];
            *(float4*)&Ks[jr][e0+4] = kr[1];
        } else {
            *(float4*)&Ks[jr][e0]   = make_float4(0.f,0.f,0.f,0.f);
            *(float4*)&Ks[jr][e0+4] = make_float4(0.f,0.f,0.f,0.f);
        }
        __syncthreads();
        int jj = kb + lane;
        u64 acc2 = 0ull;
        const u64* kr2 = (const u64*)&Ks[lane][0];
        #pragma unroll
        for (int e2 = 0; e2 < 32; e2++) FMAF2(acc2, qv2[e2], kr2[e2]);
        float lo, hi; UNPACKF2(lo, hi, acc2);
        if (jj < SEQ_) ss[w][jj] = (lo + hi) * 0.125f;
    }

    float mx = -1e30f;
    for (int j = lane; j < SEQ_; j += 32) mx = fmaxf(mx, ss[w][j]);
    #pragma unroll
    for (int o = 16; o > 0; o >>= 1) mx = fmaxf(mx, __shfl_xor_sync(0xffffffffu, mx, o));
    float sum = 0.f;
    for (int j = lane; j < SEQ_; j += 32) {
        float e = __expf(ss[w][j] - mx);
        ss[w][j] = e;
        sum += e;
    }
    #pragma unroll
    for (int o = 16; o > 0; o >>= 1) sum += __shfl_xor_sync(0xffffffffu, sum, o);
    float inv = 1.f / sum;
    if (lane > 0) ss[w][1024 + lane] = 0.f;
    __syncwarp();

    u64 o2 = 0ull;
    for (int kb = 0; kb < SEQ_; kb += 32) {
        __syncthreads();
        int j = kb + jr;
        if (j < SEQ_) {
            const float4* vr = (const float4*)&base[(size_t)j*QKV_N + 2*D_ + h*HD_ + e0];
            *(float4*)&Ks[jr][e0]   = vr[0];
            *(float4*)&Ks[jr][e0+4] = vr[1];
        } else {
            *(float4*)&Ks[jr][e0]   = make_float4(0.f,0.f,0.f,0.f);
            *(float4*)&Ks[jr][e0+4] = make_float4(0.f,0.f,0.f,0.f);
        }
        __syncthreads();
        #pragma unroll
        for (int jj = 0; jj < 32; jj++) {
            float p = ss[w][kb + jj];
            u64 p2; PACKF2(p2, p, p);
            u64 v2 = *(const u64*)&Ks[jj][2*lane];
            FMAF2(o2, p2, v2);
        }
    }

    if (qg < SEQ_) {
        float lo, hi; UNPACKF2(lo, hi, o2);
        float* orow = &out[((size_t)b*SEQ_ + qg)*D_ + h*HD_];
        *(float2*)&orow[2*lane] = make_float2(f2tf32(lo * inv), f2tf32(hi * inv));
    }
}

// ---------------- patch-embed assemble ---------------------------------------
__global__ void assemble_k(const float* __restrict__ tmp, const float* __restrict__ cls,
                           float* __restrict__ x)
{
    int idx = blockIdx.x*blockDim.x + threadIdx.x;
    if (idx >= ROWS_*D_) return;
    int d = idx % D_;
    int rp = idx / D_;
    int pos = rp % SEQ_;
    int b = rp / SEQ_;
    float val = (pos == 0) ? cls[d] : tmp[((size_t)b*N_ + pos-1)*D_ + d];
    float expo = (float)(d & ~1) * (1.f/(float)D_);
    float ang = (float)pos / powf(10000.f, expo);
    float pe = (d & 1) ? cosf(ang) : sinf(ang);
    x[idx] = val + pe;
}

// ---------------- repack per-layer QKV weights into [l][k][n] fp32 ----------
__global__ void repack_k(const float* __restrict__ wq, const float* __restrict__ wk,
                         const float* __restrict__ wv, const float* __restrict__ bq,
                         const float* __restrict__ bk, const float* __restrict__ bv,
                         float* __restrict__ pw, float* __restrict__ pb)
{
    int idx = blockIdx.x*blockDim.x + threadIdx.x;
    if (idx >= L_*D_*QKV_N) return;
    int j = idx % QKV_N;
    int t = idx / QKV_N;
    int k = t % D_;
    int l = t / D_;
    int sec = j / D_, jj = j % D_, h = jj >> 6, e = jj & 63;
    const float* w = (sec == 0) ? wq : (sec == 1) ? wk : wv;
    pw[idx] = w[(((size_t)l*H_ + h)*D_ + k)*HD_ + e];
    if (k == 0) {
        const float* bb = (sec == 0) ? bq : (sec == 1) ? bk : bv;
        pb[l*QKV_N + j] = bb[((size_t)l*H_ + h)*HD_ + e];
    }
}

// ---------------- transpose + tf32 round: dst[m][n][k] = rnd(src[m][k][n]) ---
__global__ void trT_k(const float* __restrict__ src, float* __restrict__ dst,
                      int K, int N, int total)
{
    int idx = blockIdx.x*blockDim.x + threadIdx.x;
    if (idx >= total) return;
    int nk = N*K;
    int m = idx / nk;
    int t = idx % nk;
    int n = t / K, k = t % K;
    dst[idx] = f2tf32(src[((size_t)m*K + k)*N + n]);
}

// ---------------- plain tf32 round -------------------------------------------
__global__ void rnd_k(const float* __restrict__ src, float* __restrict__ dst, int total)
{
    int idx = blockIdx.x*blockDim.x + threadIdx.x;
    if (idx >= total) return;
    dst[idx] = f2tf32(src[idx]);
}

// ---------------- classifier logits (NC=2) -----------------------------------
__global__ void logits_k(const float* __restrict__ x, const float* __restrict__ cw,
                         const float* __restrict__ cb, float* __restrict__ lg)
{
    int idx = blockIdx.x*blockDim.x + threadIdx.x;
    if (idx >= B_*N_*NC_) return;
    int c = idx & 1;
    int bn = idx >> 1;
    int n = bn % N_, b = bn / N_;
    const float4* xr = (const float4*)(x + ((size_t)b*SEQ_ + n + 1)*D_);
    float s = cb[c];
    #pragma unroll 4
    for (int d4 = 0; d4 < D_/4; d4++) {
        float4 xv = xr[d4];
        s += xv.x*cw[(d4*4+0)*NC_ + c] + xv.y*cw[(d4*4+1)*NC_ + c]
           + xv.z*cw[(d4*4+2)*NC_ + c] + xv.w*cw[(d4*4+3)*NC_ + c];
    }
    lg[idx] = s;
}

// ---------------- deconv upsample ---------------------------------------------
__global__ void up_k(const float* __restrict__ lg, const float* __restrict__ dw,
                     const float* __restrict__ db, float* __restrict__ out)
{
    int idx = blockIdx.x*blockDim.x + threadIdx.x;
    if (idx >= B_*NC_*N_*16*16) return;
    int ww = idx & 15;
    int t = idx >> 4;
    int hh = t & 15; t >>= 4;
    int n = t % N_;  t /= N_;
    int o = t & 1;   int b = t >> 1;
    float s = db[o];
    #pragma unroll
    for (int c = 0; c < NC_; c++)
        s += lg[((size_t)b*N_ + n)*NC_ + c] * dw[((c*NC_ + o)*16 + hh)*16 + ww];
    out[idx] = s;
}

// ---------------- launch ------------------------------------------------------
extern "C" void kernel_launch(void* const* d_in, const int* in_sizes, int n_in,
                              void* d_out, int out_size)
{
    const float* images  = (const float*)d_in[0];
    const float* patch_w = (const float*)d_in[2];
    const float* patch_b = (const float*)d_in[3];
    const float* cls_tok = (const float*)d_in[4];
    const float* ln1_g   = (const float*)d_in[5];
    const float* ln1_b   = (const float*)d_in[6];
    const float* wq      = (const float*)d_in[7];
    const float* bq      = (const float*)d_in[8];
    const float* wk      = (const float*)d_in[9];
    const float* bk      = (const float*)d_in[10];
    const float* wv      = (const float*)d_in[11];
    const float* bv      = (const float*)d_in[12];
    const float* wo      = (const float*)d_in[13];
    const float* bo      = (const float*)d_in[14];
    const float* ln2_g   = (const float*)d_in[15];
    const float* ln2_b   = (const float*)d_in[16];
    const float* w1      = (const float*)d_in[17];
    const float* b1      = (const float*)d_in[18];
    const float* w2      = (const float*)d_in[19];
    const float* b2      = (const float*)d_in[20];
    const float* cls_w   = (const float*)d_in[21];
    const float* cls_b   = (const float*)d_in[22];
    const float* dc_w    = (const float*)d_in[23];
    const float* dc_b    = (const float*)d_in[24];
    float* out = (float*)d_out;

    float *x, *h, *qkv, *attn, *mlp, *pw, *pb, *lg;
    float *qkvT, *woT, *w1T, *w2T, *patT, *img;
    cudaGetSymbolAddress((void**)&x,    g_x);
    cudaGetSymbolAddress((void**)&h,    g_h);
    cudaGetSymbolAddress((void**)&qkv,  g_qkv);
    cudaGetSymbolAddress((void**)&attn, g_attn);
    cudaGetSymbolAddress((void**)&mlp,  g_mlp);
    cudaGetSymbolAddress((void**)&pw,   g_pw);
    cudaGetSymbolAddress((void**)&pb,   g_pb);
    cudaGetSymbolAddress((void**)&qkvT, g_qkvT);
    cudaGetSymbolAddress((void**)&woT,  g_woT);
    cudaGetSymbolAddress((void**)&w1T,  g_w1T);
    cudaGetSymbolAddress((void**)&w2T,  g_w2T);
    cudaGetSymbolAddress((void**)&patT, g_patT);
    cudaGetSymbolAddress((void**)&img,  g_img);
    cudaGetSymbolAddress((void**)&lg,   g_lg);

    const int SMEM_SZ = 4*SBUF*4;   // 73728 B
    cudaFuncSetAttribute(gemm4_k<EPI_BIAS>, cudaFuncAttributeMaxDynamicSharedMemorySize, SMEM_SZ);
    cudaFuncSetAttribute(gemm4_k<EPI_RES>,  cudaFuncAttributeMaxDynamicSharedMemorySize, SMEM_SZ);
    cudaFuncSetAttribute(gemm4_k<EPI_GELU>, cudaFuncAttributeMaxDynamicSharedMemorySize, SMEM_SZ);

    // ---- weight prep (per launch, cheap) ----
    repack_k<<<(L_*D_*QKV_N + 255)/256, 256>>>(wq, wk, wv, bq, bk, bv, pw, pb);
    trT_k<<<(L_*QKV_N*D_ + 255)/256, 256>>>(pw,      qkvT, D_,  QKV_N, L_*QKV_N*D_);
    trT_k<<<(L_*D_*D_    + 255)/256, 256>>>(wo,      woT,  D_,  D_,    L_*D_*D_);
    trT_k<<<(L_*FF_*D_   + 255)/256, 256>>>(w1,      w1T,  D_,  FF_,   L_*FF_*D_);
    trT_k<<<(L_*D_*FF_   + 255)/256, 256>>>(w2,      w2T,  FF_, D_,    L_*D_*FF_);
    trT_k<<<(D_*256      + 255)/256, 256>>>(patch_w, patT, 256, D_,    D_*256);
    rnd_k<<<(B_*N_*256   + 255)/256, 256>>>(images,  img,  B_*N_*256);

    // ---- patch embed GEMM: (8192 x 256) @ (384 x 256)^T -> qkv (fp32 tmp) ---
    {
        dim3 g(D_/128, (B_*N_)/128);
        gemm4_k<EPI_BIAS><<<g, 128, SMEM_SZ>>>(img, patT, patch_b, nullptr, qkv,
                                               B_*N_, D_, 256);
    }
    assemble_k<<<(ROWS_*D_ + 255)/256, 256>>>(qkv, cls_tok, x);

    dim3 gq(QKV_N/128, ROWSP_/128);
    dim3 go(D_/128,    ROWSP_/128);
    dim3 g1(FF_/128,   ROWSP_/128);
    dim3 ga((SEQ_+7)/8, B_*H_);

    for (int l = 0; l < L_; l++) {
        ln_k<<<ROWS_, 128>>>(x, ln1_g + l*D_, ln1_b + l*D_, h);
        gemm4_k<EPI_BIAS><<<gq, 128, SMEM_SZ>>>(h, qkvT + (size_t)l*QKV_N*D_,
                                                pb + l*QKV_N, nullptr,
                                                qkv, ROWSP_, QKV_N, D_);
        attn3_k<<<ga, 256>>>(qkv, attn);
        gemm4_k<EPI_RES><<<go, 128, SMEM_SZ>>>(attn, woT + (size_t)l*D_*D_,
                                               bo + l*D_, x,
                                               x, ROWSP_, D_, D_);
        ln_k<<<ROWS_, 128>>>(x, ln2_g + l*D_, ln2_b + l*D_, h);
        gemm4_k<EPI_GELU><<<g1, 128, SMEM_SZ>>>(h, w1T + (size_t)l*FF_*D_,
                                                b1 + l*FF_, nullptr,
                                                mlp, ROWSP_, FF_, D_);
        gemm4_k<EPI_RES><<<go, 128, SMEM_SZ>>>(mlp, w2T + (size_t)l*D_*FF_,
                                               b2 + l*D_, x,
                                               x, ROWSP_, D_, FF_);
    }

    logits_k<<<(B_*N_*NC_ + 127)/128, 128>>>(x, cls_w, cls_b, lg);
    up_k<<<(B_*NC_*N_*256 + 255)/256, 256>>>(lg, dc_w, dc_b, out);
    (void)in_sizes; (void)n_in; (void)out_size;
}